// round 1
// baseline (speedup 1.0000x reference)
#include <cuda_runtime.h>
#include <math.h>

// Problem constants (shapes fixed by setup_inputs)
#define N_PTS 8192
#define TILE  256
#define NT    (N_PTS / TILE)        // 32 tiles per dimension
#define NTRI  (NT * (NT + 1) / 2)   // 528 upper-tri tiles
#define NFULL (NT * NT)             // 1024 full tiles
#define NBLK  (2 * NTRI + NFULL)    // 2080 blocks total

// ---------------- device scratch (no allocation allowed) ----------------
// g_wacc: [0]=U_b  [1]=sum u^2 (b) [2]=sum u*x (b) [3]=sum u*y (b)
//         [4]=U_t  [5]=sum u^2 (t) [6]=sum u*x (t) [7]=sum u*y (t)
__device__ double g_wacc[8];
// g_pacc: [0..2]=S_aa bands, [3..5]=S_bb, [6..8]=S_ab, [9]=sum dist, [10]=sum dist^2
__device__ double g_pacc[11];
__device__ float2 g_sb[N_PTS];   // scaled base points
__device__ float2 g_st[N_PTS];   // scaled target points
__device__ float  g_ub[N_PTS];   // unnormalized weights (base)
__device__ float  g_ut[N_PTS];   // unnormalized weights (target)

static __device__ __forceinline__ float ex2f(float x) {
    float r; asm("ex2.approx.ftz.f32 %0, %1;" : "=f"(r) : "f"(x)); return r;
}
static __device__ __forceinline__ float sqrtap(float x) {
    float r; asm("sqrt.approx.f32 %0, %1;" : "=f"(r) : "f"(x)); return r;
}

// valid result on thread 0; blockDim must be 256 (8 warps)
static __device__ __forceinline__ float block_reduce(float v, float* sbuf) {
    __syncthreads();  // protect sbuf across repeated calls
    #pragma unroll
    for (int o = 16; o > 0; o >>= 1) v += __shfl_down_sync(0xffffffffu, v, o);
    int warp = threadIdx.x >> 5, lane = threadIdx.x & 31;
    if (lane == 0) sbuf[warp] = v;
    __syncthreads();
    if (warp == 0) {
        v = (lane < 8) ? sbuf[lane] : 0.f;
        #pragma unroll
        for (int o = 4; o > 0; o >>= 1) v += __shfl_down_sync(0xffffffffu, v, o);
    }
    return v;
}

// ---------------- kernel 1: zero accumulators (graph replays!) ----------
__global__ void k_init() {
    int t = threadIdx.x;
    if (t < 8)  g_wacc[t] = 0.0;
    if (t < 11) g_pacc[t] = 0.0;
}

// ---------------- kernel 2: scale points, weight-net MLP, moments -------
__global__ __launch_bounds__(256) void k_weights(
    const float* __restrict__ base, const float* __restrict__ target,
    const float* __restrict__ log_scale,
    const float* __restrict__ w1, const float* __restrict__ b1,
    const float* __restrict__ w2, const float* __restrict__ b2)
{
    __shared__ float sred[8];
    int cloud = blockIdx.x >> 5;                       // 32 blocks per cloud
    int idx   = ((blockIdx.x & 31) << 8) + threadIdx.x;
    const float* pts = cloud ? target : base;

    float sx = expf(log_scale[0]);
    float sy = expf(log_scale[1]);
    float x = pts[2 * idx]     * sx;
    float y = pts[2 * idx + 1] * sy;

    // MLP: (2 -> 32 relu -> 1), w1 is (2,32) row-major, w2 is (32,1)
    float logit = b2[0];
    #pragma unroll
    for (int j = 0; j < 32; j++) {
        float h = fmaf(x, w1[j], fmaf(y, w1[32 + j], b1[j]));
        h = fmaxf(h, 0.f);
        logit = fmaf(h, w2[j], logit);
    }
    float sp = (logit > 15.f) ? logit : log1pf(__expf(logit));
    float u = sp + 1e-6f;

    if (cloud) { g_st[idx] = make_float2(x, y); g_ut[idx] = u; }
    else       { g_sb[idx] = make_float2(x, y); g_ub[idx] = u; }

    int off = cloud * 4;
    float r;
    r = block_reduce(u,     sred); if (threadIdx.x == 0) atomicAdd(&g_wacc[off + 0], (double)r);
    r = block_reduce(u * u, sred); if (threadIdx.x == 0) atomicAdd(&g_wacc[off + 1], (double)r);
    r = block_reduce(u * x, sred); if (threadIdx.x == 0) atomicAdd(&g_wacc[off + 2], (double)r);
    r = block_reduce(u * y, sred); if (threadIdx.x == 0) atomicAdd(&g_wacc[off + 3], (double)r);
}

// ---------------- kernel 3: fused pairwise kernel (aa tri, bb tri, ab full)
__global__ __launch_bounds__(256) void k_pairs(const float* __restrict__ log_sigmas)
{
    __shared__ float4 sj[TILE];
    __shared__ float  sred[8];

    // decode block -> (matrix, tile_i, tile_j)
    int b = blockIdx.x;
    int mat, ti, tj;
    if (b < 2 * NTRI) {
        mat = (b < NTRI) ? 0 : 1;
        int t = (b < NTRI) ? b : b - NTRI;
        int r = 0;
        while (t >= NT - r) { t -= NT - r; r++; }
        ti = r; tj = r + t;                      // tj >= ti
    } else {
        mat = 2;
        int t = b - 2 * NTRI;
        ti = t >> 5; tj = t & 31;
    }

    const float2* Pi = (mat == 1) ? g_st : g_sb;
    const float*  Ui = (mat == 1) ? g_ut : g_ub;
    const float2* Pj = (mat == 0) ? g_sb : g_st;
    const float*  Uj = (mat == 0) ? g_ub : g_ut;

    int tid = threadIdx.x;
    {
        int j = (tj << 8) + tid;
        float2 p = Pj[j];
        sj[tid] = make_float4(p.x, p.y, Uj[j], 0.f);
    }
    __syncthreads();

    int i = (ti << 8) + tid;
    float2 pi = Pi[i];
    float  ui = Ui[i];

    // band coefficients: exp(-d2 / (2 s^2)) = ex2(m_k * d2)
    const float L2E = 1.4426950408889634f;
    float m0, m1, m2;
    { float s = expf(log_sigmas[0]); m0 = -L2E / (2.f * s * s); }
    { float s = expf(log_sigmas[1]); m1 = -L2E / (2.f * s * s); }
    { float s = expf(log_sigmas[2]); m2 = -L2E / (2.f * s * s); }

    float a0 = 0.f, a1 = 0.f, a2 = 0.f, sd = 0.f, sq = 0.f;

    if (mat == 2) {
        // cross term: centered distance = raw diff shifted by (mu_b - mu_t);
        // dist stats use the RAW (uncentered) distance.
        float delx = (float)(g_wacc[2] / g_wacc[0] - g_wacc[6] / g_wacc[4]);
        float dely = (float)(g_wacc[3] / g_wacc[0] - g_wacc[7] / g_wacc[4]);
        #pragma unroll 4
        for (int j = 0; j < TILE; j++) {
            float4 p = sj[j];
            float dx = pi.x - p.x, dy = pi.y - p.y;
            float d2r = fmaf(dx, dx, dy * dy);
            float cx = dx - delx, cy = dy - dely;
            float d2 = fmaf(cx, cx, cy * cy);
            a0 = fmaf(p.z, ex2f(m0 * d2), a0);
            a1 = fmaf(p.z, ex2f(m1 * d2), a1);
            a2 = fmaf(p.z, ex2f(m2 * d2), a2);
            sq += d2r;
            sd += sqrtap(d2r);
        }
    } else {
        // same-cloud: centering cancels -> raw scaled distance
        #pragma unroll 4
        for (int j = 0; j < TILE; j++) {
            float4 p = sj[j];
            float dx = pi.x - p.x, dy = pi.y - p.y;
            float d2 = fmaf(dx, dx, dy * dy);
            a0 = fmaf(p.z, ex2f(m0 * d2), a0);
            a1 = fmaf(p.z, ex2f(m1 * d2), a1);
            a2 = fmaf(p.z, ex2f(m2 * d2), a2);
        }
    }

    float f = (mat != 2 && ti != tj) ? 2.f : 1.f;  // symmetric off-diag tiles counted twice
    f *= ui;
    a0 *= f; a1 *= f; a2 *= f;

    float r;
    r = block_reduce(a0, sred); if (tid == 0) atomicAdd(&g_pacc[mat * 3 + 0], (double)r);
    r = block_reduce(a1, sred); if (tid == 0) atomicAdd(&g_pacc[mat * 3 + 1], (double)r);
    r = block_reduce(a2, sred); if (tid == 0) atomicAdd(&g_pacc[mat * 3 + 2], (double)r);
    if (mat == 2) {
        r = block_reduce(sd, sred); if (tid == 0) atomicAdd(&g_pacc[9],  (double)r);
        r = block_reduce(sq, sred); if (tid == 0) atomicAdd(&g_pacc[10], (double)r);
    }
}

// ---------------- kernel 4: stats, gating MLP, final scalar -------------
__global__ void k_final(const float* __restrict__ gw1, const float* __restrict__ gb1,
                        const float* __restrict__ gw2, const float* __restrict__ gb2,
                        const float* __restrict__ bias, float* __restrict__ out)
{
    double Ub = g_wacc[0], U2b = g_wacc[1];
    double Ut = g_wacc[4], U2t = g_wacc[5];
    double n  = (double)N_PTS;
    double NM = n * n;

    double meand = g_pacc[9] / NM;
    double vard  = (g_pacc[10] - g_pacc[9] * g_pacc[9] / NM) / (NM - 1.0);
    // var of normalized weights w = u/U, sum(w)=1:
    double wvar = (U2b / (Ub * Ub) - 1.0 / n) / (n - 1.0)
                + (U2t / (Ut * Ut) - 1.0 / n) / (n - 1.0);

    float stats[4] = { (float)meand, (float)vard, 0.f, (float)wvar };

    float L[3];
    #pragma unroll
    for (int k = 0; k < 3; k++)
        L[k] = (float)(g_pacc[k]     / (Ub * Ub)
                     + g_pacc[3 + k] / (Ut * Ut)
                     - 2.0 * g_pacc[6 + k] / (Ub * Ut));

    // gating MLP: (4 -> 32 relu -> 3), gw1 is (4,32), gw2 is (32,3)
    float h[32];
    #pragma unroll
    for (int j = 0; j < 32; j++) {
        float v = gb1[j];
        #pragma unroll
        for (int d = 0; d < 4; d++) v = fmaf(stats[d], gw1[d * 32 + j], v);
        h[j] = fmaxf(v, 0.f);
    }
    float g[3], gs = 0.f;
    #pragma unroll
    for (int s = 0; s < 3; s++) {
        float v = gb2[s];
        #pragma unroll
        for (int j = 0; j < 32; j++) v = fmaf(h[j], gw2[j * 3 + s], v);
        float sp = (v > 15.f) ? v : log1pf(__expf(v));
        g[s] = sp; gs += sp;
    }
    float res = bias[0];
    #pragma unroll
    for (int s = 0; s < 3; s++) res = fmaf(g[s] / gs, L[s], res);
    out[0] = res;
}

// ---------------- launch ------------------------------------------------
extern "C" void kernel_launch(void* const* d_in, const int* in_sizes, int n_in,
                              void* d_out, int out_size)
{
    const float* base       = (const float*)d_in[0];
    const float* target     = (const float*)d_in[1];
    const float* log_sigmas = (const float*)d_in[2];
    const float* log_scale  = (const float*)d_in[3];
    const float* wn_w1      = (const float*)d_in[4];
    const float* wn_b1      = (const float*)d_in[5];
    const float* wn_w2      = (const float*)d_in[6];
    const float* wn_b2      = (const float*)d_in[7];
    const float* g_w1       = (const float*)d_in[8];
    const float* g_b1       = (const float*)d_in[9];
    const float* g_w2       = (const float*)d_in[10];
    const float* g_b2       = (const float*)d_in[11];
    const float* bias       = (const float*)d_in[12];

    k_init<<<1, 32>>>();
    k_weights<<<64, 256>>>(base, target, log_scale, wn_w1, wn_b1, wn_w2, wn_b2);
    k_pairs<<<NBLK, 256>>>(log_sigmas);
    k_final<<<1, 1>>>(g_w1, g_b1, g_w2, g_b2, bias, (float*)d_out);
}

// round 4
// speedup vs baseline: 1.1750x; 1.1750x over previous
#include <cuda_runtime.h>
#include <math.h>

#define N_PTS 8192
#define TILE  256
#define NT    (N_PTS / TILE)        // 32
#define NTRI  (NT * (NT + 1) / 2)   // 528
#define NBLK  (2 * NTRI + NT * NT)  // 2080

typedef unsigned long long u64;

// ---------------- packed f32x2 helpers (sm_100+) ------------------------
static __device__ __forceinline__ u64 pack2(float lo, float hi) {
    u64 r; asm("mov.b64 %0, {%1, %2};" : "=l"(r) : "f"(lo), "f"(hi)); return r;
}
static __device__ __forceinline__ void unpack2(u64 v, float& lo, float& hi) {
    asm("mov.b64 {%0, %1}, %2;" : "=f"(lo), "=f"(hi) : "l"(v));
}
static __device__ __forceinline__ u64 fma2(u64 a, u64 b, u64 c) {
    u64 r; asm("fma.rn.f32x2 %0, %1, %2, %3;" : "=l"(r) : "l"(a), "l"(b), "l"(c)); return r;
}
static __device__ __forceinline__ u64 mul2(u64 a, u64 b) {
    u64 r; asm("mul.rn.f32x2 %0, %1, %2;" : "=l"(r) : "l"(a), "l"(b)); return r;
}
static __device__ __forceinline__ u64 add2(u64 a, u64 b) {
    u64 r; asm("add.rn.f32x2 %0, %1, %2;" : "=l"(r) : "l"(a), "l"(b)); return r;
}
static __device__ __forceinline__ u64 sub2(u64 a, u64 b) {
    u64 r; asm("sub.rn.f32x2 %0, %1, %2;" : "=l"(r) : "l"(a), "l"(b)); return r;
}
static __device__ __forceinline__ float ex2f(float x) {
    float r; asm("ex2.approx.ftz.f32 %0, %1;" : "=f"(r) : "f"(x)); return r;
}
static __device__ __forceinline__ float sqrtap(float x) {
    float r; asm("sqrt.approx.f32 %0, %1;" : "=f"(r) : "f"(x)); return r;
}

// ---------------- device scratch ---------------------------------------
// per cloud c (0=base,1=target), offset o=c*7:
//   o+0: U=sum u, o+1: sum u^2, o+2: sum u*x, o+3: sum u*y,
//   o+4: sum x,  o+5: sum y,   o+6: sum (x^2+y^2)
__device__ double g_wacc[14];
// 0..2 = S_aa bands, 3..5 = S_bb, 6..8 = S_ab, 9 = sum dist
__device__ double g_pacc[10];
__device__ float g_px[2][N_PTS];
__device__ float g_py[2][N_PTS];
__device__ float g_u[2][N_PTS];

// valid on thread 0; blockDim 256
static __device__ __forceinline__ float block_reduce(float v, float* sbuf) {
    __syncthreads();
    #pragma unroll
    for (int o = 16; o > 0; o >>= 1) v += __shfl_down_sync(0xffffffffu, v, o);
    int warp = threadIdx.x >> 5, lane = threadIdx.x & 31;
    if (lane == 0) sbuf[warp] = v;
    __syncthreads();
    if (warp == 0) {
        v = (lane < 8) ? sbuf[lane] : 0.f;
        #pragma unroll
        for (int o = 4; o > 0; o >>= 1) v += __shfl_down_sync(0xffffffffu, v, o);
    }
    return v;
}

// ---------------- kernel 1: zero accumulators --------------------------
__global__ void k_init() {
    int t = threadIdx.x;
    if (t < 14) g_wacc[t] = 0.0;
    if (t < 10) g_pacc[t] = 0.0;
}

// ---------------- kernel 2: scale, weight-net, moments ------------------
__global__ __launch_bounds__(256) void k_weights(
    const float* __restrict__ base, const float* __restrict__ target,
    const float* __restrict__ log_scale,
    const float* __restrict__ w1, const float* __restrict__ b1,
    const float* __restrict__ w2, const float* __restrict__ b2)
{
    __shared__ float sred[8];
    int cloud = blockIdx.x >> 5;
    int idx   = ((blockIdx.x & 31) << 8) + threadIdx.x;
    const float* pts = cloud ? target : base;

    float sx = expf(log_scale[0]);
    float sy = expf(log_scale[1]);
    float x = pts[2 * idx]     * sx;
    float y = pts[2 * idx + 1] * sy;

    float logit = b2[0];
    #pragma unroll
    for (int j = 0; j < 32; j++) {
        float h = fmaf(x, w1[j], fmaf(y, w1[32 + j], b1[j]));
        h = fmaxf(h, 0.f);
        logit = fmaf(h, w2[j], logit);
    }
    float sp = (logit > 15.f) ? logit : log1pf(__expf(logit));
    float u = sp + 1e-6f;

    g_px[cloud][idx] = x;
    g_py[cloud][idx] = y;
    g_u[cloud][idx]  = u;

    int o = cloud * 7;
    float r;
    r = block_reduce(u,               sred); if (threadIdx.x == 0) atomicAdd(&g_wacc[o + 0], (double)r);
    r = block_reduce(u * u,           sred); if (threadIdx.x == 0) atomicAdd(&g_wacc[o + 1], (double)r);
    r = block_reduce(u * x,           sred); if (threadIdx.x == 0) atomicAdd(&g_wacc[o + 2], (double)r);
    r = block_reduce(u * y,           sred); if (threadIdx.x == 0) atomicAdd(&g_wacc[o + 3], (double)r);
    r = block_reduce(x,               sred); if (threadIdx.x == 0) atomicAdd(&g_wacc[o + 4], (double)r);
    r = block_reduce(y,               sred); if (threadIdx.x == 0) atomicAdd(&g_wacc[o + 5], (double)r);
    r = block_reduce(fmaf(x,x,y*y),   sred); if (threadIdx.x == 0) atomicAdd(&g_wacc[o + 6], (double)r);
}

// ---------------- kernel 3: fused pairwise -----------------------------
__global__ __launch_bounds__(256) void k_pairs(const float* __restrict__ log_sigmas)
{
    __shared__ alignas(8) float s_x[TILE];
    __shared__ alignas(8) float s_y[TILE];
    __shared__ alignas(8) float s_q[TILE];   // qj (tri) or kj (ab)
    __shared__ alignas(8) float s_w[TILE];
    __shared__ float sred[8];

    // ---- decode block: interleave tri / full tiles for pipe balance ----
    int b = blockIdx.x;
    int mat, ti, tj;
    int t = -1;
    if (b < 2048) {
        if (b & 1) { int f = b >> 1; mat = 2; ti = f >> 5; tj = f & 31; }
        else t = b >> 1;
    } else t = 1024 + (b - 2048);
    if (t >= 0) {
        mat = (t < NTRI) ? 0 : 1;
        if (t >= NTRI) t -= NTRI;
        int r = 0;
        while (t >= NT - r) { t -= NT - r; r++; }
        ti = r; tj = r + t;
    }

    // ---- band coefficients (log2 domain) ----
    const float L2E = 1.4426950408889634f;
    float s0 = expf(log_sigmas[0]);
    float s1 = expf(log_sigmas[1]);
    float s2 = expf(log_sigmas[2]);
    float m0 = -L2E / (2.f * s0 * s0);
    float m1 = -L2E / (2.f * s1 * s1);
    float m2 = -L2E / (2.f * s2 * s2);
    bool fast = (fabsf(m1 / m2 - 4.f) < 4e-4f) && (fabsf(m0 / m2 - 16.f) < 1.6e-3f);

    int ci_cloud = (mat == 1) ? 1 : 0;
    int cj_cloud = (mat == 0) ? 0 : 1;

    float delx = 0.f, dely = 0.f, del2 = 0.f;
    if (mat == 2) {
        delx = (float)(g_wacc[2] / g_wacc[0] - g_wacc[9]  / g_wacc[7]);
        dely = (float)(g_wacc[3] / g_wacc[0] - g_wacc[10] / g_wacc[7]);
        del2 = delx * delx + dely * dely;
    }

    int tid = threadIdx.x;
    {
        int j = (tj << 8) + tid;
        float xj = g_px[cj_cloud][j], yj = g_py[cj_cloud][j];
        s_x[tid] = xj; s_y[tid] = yj;
        s_w[tid] = g_u[cj_cloud][j];
        s_q[tid] = (mat == 2) ? 2.f * (delx * xj + dely * yj)
                              : m2 * fmaf(xj, xj, yj * yj);
    }
    __syncthreads();

    int i = (ti << 8) + tid;
    float xi = g_px[ci_cloud][i], yi = g_py[ci_cloud][i], ui = g_u[ci_cloud][i];

    float a0s, a1s, a2s, sds = 0.f;

    if (fast) {
        u64 A0 = 0, A1 = 0, A2 = 0, SD = 0;  // packed {0.f,0.f}
        if (mat != 2) {
            // same-cloud: arg = qi + qj + xi2*xj + yi2*yj  (== m2*d2, <= 0)
            float qi = m2 * fmaf(xi, xi, yi * yi);
            u64 X2 = pack2(-2.f * m2 * xi, -2.f * m2 * xi);
            u64 Y2 = pack2(-2.f * m2 * yi, -2.f * m2 * yi);
            u64 QI = pack2(qi, qi);
            #pragma unroll 4
            for (int j = 0; j < TILE; j += 2) {
                u64 xj = *(const u64*)&s_x[j];
                u64 yj = *(const u64*)&s_y[j];
                u64 qj = *(const u64*)&s_q[j];
                u64 wj = *(const u64*)&s_w[j];
                u64 arg = fma2(X2, xj, fma2(Y2, yj, qj));
                arg = add2(arg, QI);
                float al, ah; unpack2(arg, al, ah);
                u64 e2 = pack2(ex2f(al), ex2f(ah));
                u64 s  = mul2(e2, e2);
                u64 e1 = mul2(s, s);          // e2^4
                u64 s2p = mul2(e1, e1);
                u64 e0 = mul2(s2p, s2p);      // e2^16
                A2 = fma2(wj, e2, A2);
                A1 = fma2(wj, e1, A1);
                A0 = fma2(wj, e0, A0);
            }
        } else {
            // cross: raw d2r for stats, centered d2c = d2r + kj + ci for kernel
            float cim = m2 * (del2 - 2.f * (delx * xi + dely * yi));  // m2*ci
            u64 PX = pack2(xi, xi), PY = pack2(yi, yi);
            u64 CIM = pack2(cim, cim), M2 = pack2(m2, m2);
            #pragma unroll 4
            for (int j = 0; j < TILE; j += 2) {
                u64 xj = *(const u64*)&s_x[j];
                u64 yj = *(const u64*)&s_y[j];
                u64 kj = *(const u64*)&s_q[j];
                u64 wj = *(const u64*)&s_w[j];
                u64 dx = sub2(PX, xj), dy = sub2(PY, yj);
                u64 d2r = fma2(dx, dx, mul2(dy, dy));
                float dl, dh; unpack2(d2r, dl, dh);
                SD = add2(SD, pack2(sqrtap(dl), sqrtap(dh)));
                u64 arg = fma2(add2(d2r, kj), M2, CIM);
                float al, ah; unpack2(arg, al, ah);
                u64 e2 = pack2(ex2f(al), ex2f(ah));
                u64 s  = mul2(e2, e2);
                u64 e1 = mul2(s, s);
                u64 s2p = mul2(e1, e1);
                u64 e0 = mul2(s2p, s2p);
                A2 = fma2(wj, e2, A2);
                A1 = fma2(wj, e1, A1);
                A0 = fma2(wj, e0, A0);
            }
        }
        float l, h;
        unpack2(A0, l, h); a0s = l + h;
        unpack2(A1, l, h); a1s = l + h;
        unpack2(A2, l, h); a2s = l + h;
        unpack2(SD, l, h); sds = l + h;
    } else {
        // generic fallback: 3 independent exps per pair
        a0s = a1s = a2s = 0.f;
        if (mat != 2) {
            for (int j = 0; j < TILE; j++) {
                float dx = xi - s_x[j], dy = yi - s_y[j];
                float d2 = fmaf(dx, dx, dy * dy);
                float w = s_w[j];
                a0s = fmaf(w, ex2f(m0 * d2), a0s);
                a1s = fmaf(w, ex2f(m1 * d2), a1s);
                a2s = fmaf(w, ex2f(m2 * d2), a2s);
            }
        } else {
            for (int j = 0; j < TILE; j++) {
                float dx = xi - s_x[j], dy = yi - s_y[j];
                float d2r = fmaf(dx, dx, dy * dy);
                sds += sqrtap(d2r);
                float cx = dx - delx, cy = dy - dely;
                float d2 = fmaf(cx, cx, cy * cy);
                float w = s_w[j];
                a0s = fmaf(w, ex2f(m0 * d2), a0s);
                a1s = fmaf(w, ex2f(m1 * d2), a1s);
                a2s = fmaf(w, ex2f(m2 * d2), a2s);
            }
        }
    }

    float f = (mat != 2 && ti != tj) ? 2.f : 1.f;
    f *= ui;
    a0s *= f; a1s *= f; a2s *= f;

    float r;
    r = block_reduce(a0s, sred); if (tid == 0) atomicAdd(&g_pacc[mat * 3 + 0], (double)r);
    r = block_reduce(a1s, sred); if (tid == 0) atomicAdd(&g_pacc[mat * 3 + 1], (double)r);
    r = block_reduce(a2s, sred); if (tid == 0) atomicAdd(&g_pacc[mat * 3 + 2], (double)r);
    if (mat == 2) {
        r = block_reduce(sds, sred); if (tid == 0) atomicAdd(&g_pacc[9], (double)r);
    }
}

// ---------------- kernel 4: stats + gating (one warp) -------------------
__global__ void k_final(const float* __restrict__ gw1, const float* __restrict__ gb1,
                        const float* __restrict__ gw2, const float* __restrict__ gb2,
                        const float* __restrict__ bias, float* __restrict__ out)
{
    int lane = threadIdx.x;
    double Ub = g_wacc[0], U2b = g_wacc[1];
    double Ut = g_wacc[7], U2t = g_wacc[8];
    double n  = (double)N_PTS;
    double NM = n * n;

    // sum of squared raw distances from moments (exact identity)
    double sum_d2 = n * g_wacc[6] + n * g_wacc[13]
                  - 2.0 * (g_wacc[4] * g_wacc[11] + g_wacc[5] * g_wacc[12]);
    double sd = g_pacc[9];
    double meand = sd / NM;
    double vard  = (sum_d2 - sd * sd / NM) / (NM - 1.0);
    double wvar = (U2b / (Ub * Ub) - 1.0 / n) / (n - 1.0)
                + (U2t / (Ut * Ut) - 1.0 / n) / (n - 1.0);

    float stats[4] = { (float)meand, (float)vard, 0.f, (float)wvar };

    float L[3];
    #pragma unroll
    for (int k = 0; k < 3; k++)
        L[k] = (float)(g_pacc[k]     / (Ub * Ub)
                     + g_pacc[3 + k] / (Ut * Ut)
                     - 2.0 * g_pacc[6 + k] / (Ub * Ut));

    // hidden unit per lane
    float v = gb1[lane];
    #pragma unroll
    for (int d = 0; d < 4; d++) v = fmaf(stats[d], gw1[d * 32 + lane], v);
    float h = fmaxf(v, 0.f);

    float g[3], gs = 0.f;
    #pragma unroll
    for (int s = 0; s < 3; s++) {
        float p = h * gw2[lane * 3 + s];
        #pragma unroll
        for (int o = 16; o > 0; o >>= 1) p += __shfl_xor_sync(0xffffffffu, p, o);
        p += gb2[s];
        float sp = (p > 15.f) ? p : log1pf(__expf(p));
        g[s] = sp; gs += sp;
    }
    if (lane == 0) {
        float res = bias[0];
        #pragma unroll
        for (int s = 0; s < 3; s++) res = fmaf(g[s] / gs, L[s], res);
        out[0] = res;
    }
}

// ---------------- launch ------------------------------------------------
extern "C" void kernel_launch(void* const* d_in, const int* in_sizes, int n_in,
                              void* d_out, int out_size)
{
    const float* base       = (const float*)d_in[0];
    const float* target     = (const float*)d_in[1];
    const float* log_sigmas = (const float*)d_in[2];
    const float* log_scale  = (const float*)d_in[3];
    const float* wn_w1      = (const float*)d_in[4];
    const float* wn_b1      = (const float*)d_in[5];
    const float* wn_w2      = (const float*)d_in[6];
    const float* wn_b2      = (const float*)d_in[7];
    const float* g_w1       = (const float*)d_in[8];
    const float* g_b1       = (const float*)d_in[9];
    const float* g_w2       = (const float*)d_in[10];
    const float* g_b2       = (const float*)d_in[11];
    const float* bias       = (const float*)d_in[12];

    k_init<<<1, 32>>>();
    k_weights<<<64, 256>>>(base, target, log_scale, wn_w1, wn_b1, wn_w2, wn_b2);
    k_pairs<<<NBLK, 256>>>(log_sigmas);
    k_final<<<1, 32>>>(g_w1, g_b1, g_w2, g_b2, bias, (float*)d_out);
}

// round 7
// speedup vs baseline: 1.2615x; 1.0736x over previous
#include <cuda_runtime.h>
#include <math.h>

#define N_PTS 8192
#define TILE  256
#define NT    32
#define NTRI  528        // NT*(NT+1)/2
#define NBLK  2080       // 2*NTRI + NT*NT

typedef unsigned long long u64;

// ---------------- packed f32x2 helpers (sm_100+) ------------------------
static __device__ __forceinline__ u64 pack2(float lo, float hi) {
    u64 r; asm("mov.b64 %0, {%1, %2};" : "=l"(r) : "f"(lo), "f"(hi)); return r;
}
static __device__ __forceinline__ void unpack2(u64 v, float& lo, float& hi) {
    asm("mov.b64 {%0, %1}, %2;" : "=f"(lo), "=f"(hi) : "l"(v));
}
static __device__ __forceinline__ u64 fma2(u64 a, u64 b, u64 c) {
    u64 r; asm("fma.rn.f32x2 %0, %1, %2, %3;" : "=l"(r) : "l"(a), "l"(b), "l"(c)); return r;
}
static __device__ __forceinline__ u64 mul2(u64 a, u64 b) {
    u64 r; asm("mul.rn.f32x2 %0, %1, %2;" : "=l"(r) : "l"(a), "l"(b)); return r;
}
static __device__ __forceinline__ u64 add2(u64 a, u64 b) {
    u64 r; asm("add.rn.f32x2 %0, %1, %2;" : "=l"(r) : "l"(a), "l"(b)); return r;
}
static __device__ __forceinline__ u64 sub2(u64 a, u64 b) {
    u64 r; asm("sub.rn.f32x2 %0, %1, %2;" : "=l"(r) : "l"(a), "l"(b)); return r;
}
static __device__ __forceinline__ float ex2f(float x) {
    float r; asm("ex2.approx.ftz.f32 %0, %1;" : "=f"(r) : "f"(x)); return r;
}
static __device__ __forceinline__ float sqrtap(float x) {
    float r; asm("sqrt.approx.f32 %0, %1;" : "=f"(r) : "f"(x)); return r;
}
// fast double reciprocal: float RCP seed + 2 Newton steps (~1e-16 rel)
static __device__ __forceinline__ double frcp(double x) {
    float rf; asm("rcp.approx.f32 %0, %1;" : "=f"(rf) : "f"((float)x));
    double r = (double)rf;
    r = r * (2.0 - x * r);
    r = r * (2.0 - x * r);
    return r;
}
static __device__ __forceinline__ double ldv(const double* p) {
    return *(volatile const double*)p;
}

// ---------------- device scratch ---------------------------------------
// per cloud c (0=base,1=target), offset o=c*7:
//   o+0: sum u, o+1: sum u^2, o+2: sum u*x, o+3: sum u*y,
//   o+4: sum x, o+5: sum y,   o+6: sum (x^2+y^2)
__device__ double g_wacc[14];
// 0..2 = S_aa bands, 3..5 = S_bb, 6..8 = S_ab, 9 = sum dist
__device__ double g_pacc[10];
__device__ float g_px[2][N_PTS];
__device__ float g_py[2][N_PTS];
__device__ float g_u[2][N_PTS];
// precomputed uniforms: 0:delx 1:dely 2:m0 3:m1 4:m2 5:fast 6:del2
__device__ float g_cc[8];
__device__ unsigned g_ctr[2];

// valid on thread 0; works for blockDim 256 (8 warps) or 128 (4 warps)
template<int NW>
static __device__ __forceinline__ float block_reduce(float v, float* sbuf) {
    __syncthreads();
    #pragma unroll
    for (int o = 16; o > 0; o >>= 1) v += __shfl_down_sync(0xffffffffu, v, o);
    int warp = threadIdx.x >> 5, lane = threadIdx.x & 31;
    if (lane == 0) sbuf[warp] = v;
    __syncthreads();
    if (warp == 0) {
        v = (lane < NW) ? sbuf[lane] : 0.f;
        #pragma unroll
        for (int o = NW / 2; o > 0; o >>= 1) v += __shfl_down_sync(0xffffffffu, v, o);
    }
    return v;
}

// ---------------- kernel 1: zero accumulators --------------------------
__global__ void k_init() {
    int t = threadIdx.x;
    if (t < 14) g_wacc[t] = 0.0;
    if (t < 10) g_pacc[t] = 0.0;
    if (t < 2)  g_ctr[t]  = 0u;
}

// ---------------- kernel 2: scale, weight-net, moments, uniforms --------
__global__ __launch_bounds__(256) void k_weights(
    const float* __restrict__ base, const float* __restrict__ target,
    const float* __restrict__ log_scale, const float* __restrict__ log_sigmas,
    const float* __restrict__ w1, const float* __restrict__ b1,
    const float* __restrict__ w2, const float* __restrict__ b2)
{
    __shared__ float sred[8];
    __shared__ int slast;
    if (threadIdx.x == 0) slast = 0;
    int cloud = blockIdx.x >> 5;
    int idx   = ((blockIdx.x & 31) << 8) + threadIdx.x;
    const float* pts = cloud ? target : base;

    float sx = expf(log_scale[0]);
    float sy = expf(log_scale[1]);
    float x = pts[2 * idx]     * sx;
    float y = pts[2 * idx + 1] * sy;

    float logit = b2[0];
    #pragma unroll
    for (int j = 0; j < 32; j++) {
        float h = fmaf(x, w1[j], fmaf(y, w1[32 + j], b1[j]));
        h = fmaxf(h, 0.f);
        logit = fmaf(h, w2[j], logit);
    }
    float sp = (logit > 15.f) ? logit : log1pf(__expf(logit));
    float u = sp + 1e-6f;

    g_px[cloud][idx] = x;
    g_py[cloud][idx] = y;
    g_u[cloud][idx]  = u;

    int o = cloud * 7;
    float r;
    r = block_reduce<8>(u,             sred); if (threadIdx.x == 0) atomicAdd(&g_wacc[o + 0], (double)r);
    r = block_reduce<8>(u * u,         sred); if (threadIdx.x == 0) atomicAdd(&g_wacc[o + 1], (double)r);
    r = block_reduce<8>(u * x,         sred); if (threadIdx.x == 0) atomicAdd(&g_wacc[o + 2], (double)r);
    r = block_reduce<8>(u * y,         sred); if (threadIdx.x == 0) atomicAdd(&g_wacc[o + 3], (double)r);
    r = block_reduce<8>(x,             sred); if (threadIdx.x == 0) atomicAdd(&g_wacc[o + 4], (double)r);
    r = block_reduce<8>(y,             sred); if (threadIdx.x == 0) atomicAdd(&g_wacc[o + 5], (double)r);
    r = block_reduce<8>(fmaf(x,x,y*y), sred); if (threadIdx.x == 0) atomicAdd(&g_wacc[o + 6], (double)r);

    if (threadIdx.x == 0) {
        __threadfence();
        unsigned old = atomicAdd(&g_ctr[0], 1u);
        slast = (old == 63u);
    }
    __syncthreads();
    if (slast && threadIdx.x == 0) {
        __threadfence();
        double Ub  = ldv(&g_wacc[0]), Ut = ldv(&g_wacc[7]);
        double iUb = frcp(Ub), iUt = frcp(Ut);
        float delx = (float)(ldv(&g_wacc[2]) * iUb - ldv(&g_wacc[9])  * iUt);
        float dely = (float)(ldv(&g_wacc[3]) * iUb - ldv(&g_wacc[10]) * iUt);
        const float L2E = 1.4426950408889634f;
        float s0 = expf(log_sigmas[0]);
        float s1 = expf(log_sigmas[1]);
        float s2 = expf(log_sigmas[2]);
        float m0 = -L2E / (2.f * s0 * s0);
        float m1 = -L2E / (2.f * s1 * s1);
        float m2 = -L2E / (2.f * s2 * s2);
        bool fast = (fabsf(m1 / m2 - 4.f) < 4e-4f) && (fabsf(m0 / m2 - 16.f) < 1.6e-3f);
        g_cc[0] = delx; g_cc[1] = dely;
        g_cc[2] = m0;   g_cc[3] = m1;   g_cc[4] = m2;
        g_cc[5] = fast ? 1.f : 0.f;
        g_cc[6] = delx * delx + dely * dely;
    }
}

// ---------------- kernel 3: fused pairwise + finalize -------------------
__global__ __launch_bounds__(128) void k_pairs(
    const float* __restrict__ gw1, const float* __restrict__ gb1,
    const float* __restrict__ gw2, const float* __restrict__ gb2,
    const float* __restrict__ bias, float* __restrict__ out)
{
    __shared__ alignas(8) float s_x[TILE];
    __shared__ alignas(8) float s_y[TILE];
    __shared__ alignas(8) float s_q[TILE];   // qj (tri) or kj (ab)
    __shared__ alignas(8) float s_w[TILE];
    __shared__ float sred[4];
    __shared__ int slast;
    if (threadIdx.x == 0) slast = 0;

    // ---- decode block: interleave tri / full tiles for pipe balance ----
    int b = blockIdx.x;
    int mat, ti, tj;
    int t = -1;
    if (b < 2048) {
        if (b & 1) { int f = b >> 1; mat = 2; ti = f >> 5; tj = f & 31; }
        else t = b >> 1;
    } else t = 1024 + (b - 2048);
    if (t >= 0) {
        mat = (t < NTRI) ? 0 : 1;
        if (t >= NTRI) t -= NTRI;
        int r = 0;
        while (t >= NT - r) { t -= NT - r; r++; }
        ti = r; tj = r + t;
    }

    float m0 = g_cc[2], m1 = g_cc[3], m2 = g_cc[4];
    bool fast = (g_cc[5] != 0.f);
    float delx = g_cc[0], dely = g_cc[1], del2 = g_cc[6];

    int ci_cloud = (mat == 1) ? 1 : 0;
    int cj_cloud = (mat == 0) ? 0 : 1;

    int tid = threadIdx.x;
    #pragma unroll
    for (int tt = tid; tt < TILE; tt += 128) {
        int j = (tj << 8) + tt;
        float xj = g_px[cj_cloud][j], yj = g_py[cj_cloud][j];
        s_x[tt] = xj; s_y[tt] = yj;
        s_w[tt] = g_u[cj_cloud][j];
        s_q[tt] = (mat == 2) ? 2.f * (delx * xj + dely * yj)
                             : m2 * fmaf(xj, xj, yj * yj);
    }
    __syncthreads();

    // two i rows per thread
    int i0 = (ti << 8) + tid, i1 = i0 + 128;
    float x0 = g_px[ci_cloud][i0], y0 = g_py[ci_cloud][i0], u0 = g_u[ci_cloud][i0];
    float x1 = g_px[ci_cloud][i1], y1 = g_py[ci_cloud][i1], u1 = g_u[ci_cloud][i1];

    float r00, r10, r20, r01, r11, r21, sds = 0.f;

    if (fast) {
        u64 A00 = 0, A10 = 0, A20 = 0, A01 = 0, A11 = 0, A21 = 0, SD = 0;
        if (mat != 2) {
            float q0 = m2 * fmaf(x0, x0, y0 * y0);
            float q1 = m2 * fmaf(x1, x1, y1 * y1);
            u64 X20 = pack2(-2.f * m2 * x0, -2.f * m2 * x0);
            u64 Y20 = pack2(-2.f * m2 * y0, -2.f * m2 * y0);
            u64 QI0 = pack2(q0, q0);
            u64 X21 = pack2(-2.f * m2 * x1, -2.f * m2 * x1);
            u64 Y21 = pack2(-2.f * m2 * y1, -2.f * m2 * y1);
            u64 QI1 = pack2(q1, q1);
            #pragma unroll 4
            for (int j = 0; j < TILE; j += 2) {
                u64 xj = *(const u64*)&s_x[j];
                u64 yj = *(const u64*)&s_y[j];
                u64 qj = *(const u64*)&s_q[j];
                u64 wj = *(const u64*)&s_w[j];
                u64 arg0 = add2(fma2(X20, xj, fma2(Y20, yj, qj)), QI0);
                u64 arg1 = add2(fma2(X21, xj, fma2(Y21, yj, qj)), QI1);
                float l0, h0, l1, h1;
                unpack2(arg0, l0, h0); unpack2(arg1, l1, h1);
                u64 e2a = pack2(ex2f(l0), ex2f(h0));
                u64 e2b = pack2(ex2f(l1), ex2f(h1));
                u64 sa = mul2(e2a, e2a), e1a = mul2(sa, sa);
                u64 ta = mul2(e1a, e1a), e0a = mul2(ta, ta);
                u64 sb = mul2(e2b, e2b), e1b = mul2(sb, sb);
                u64 tb = mul2(e1b, e1b), e0b = mul2(tb, tb);
                A20 = fma2(wj, e2a, A20); A10 = fma2(wj, e1a, A10); A00 = fma2(wj, e0a, A00);
                A21 = fma2(wj, e2b, A21); A11 = fma2(wj, e1b, A11); A01 = fma2(wj, e0b, A01);
            }
        } else {
            float c0 = m2 * (del2 - 2.f * (delx * x0 + dely * y0));
            float c1 = m2 * (del2 - 2.f * (delx * x1 + dely * y1));
            u64 PX0 = pack2(x0, x0), PY0 = pack2(y0, y0), CI0 = pack2(c0, c0);
            u64 PX1 = pack2(x1, x1), PY1 = pack2(y1, y1), CI1 = pack2(c1, c1);
            u64 M2 = pack2(m2, m2);
            #pragma unroll 4
            for (int j = 0; j < TILE; j += 2) {
                u64 xj = *(const u64*)&s_x[j];
                u64 yj = *(const u64*)&s_y[j];
                u64 kj = *(const u64*)&s_q[j];
                u64 wj = *(const u64*)&s_w[j];
                // i0
                u64 dx0 = sub2(PX0, xj), dy0 = sub2(PY0, yj);
                u64 d2r0 = fma2(dx0, dx0, mul2(dy0, dy0));
                float dl0, dh0; unpack2(d2r0, dl0, dh0);
                SD = add2(SD, pack2(sqrtap(dl0), sqrtap(dh0)));
                u64 arg0 = fma2(add2(d2r0, kj), M2, CI0);
                // i1
                u64 dx1 = sub2(PX1, xj), dy1 = sub2(PY1, yj);
                u64 d2r1 = fma2(dx1, dx1, mul2(dy1, dy1));
                float dl1, dh1; unpack2(d2r1, dl1, dh1);
                SD = add2(SD, pack2(sqrtap(dl1), sqrtap(dh1)));
                u64 arg1 = fma2(add2(d2r1, kj), M2, CI1);
                float l0, h0, l1, h1;
                unpack2(arg0, l0, h0); unpack2(arg1, l1, h1);
                u64 e2a = pack2(ex2f(l0), ex2f(h0));
                u64 e2b = pack2(ex2f(l1), ex2f(h1));
                u64 sa = mul2(e2a, e2a), e1a = mul2(sa, sa);
                u64 ta = mul2(e1a, e1a), e0a = mul2(ta, ta);
                u64 sb = mul2(e2b, e2b), e1b = mul2(sb, sb);
                u64 tb = mul2(e1b, e1b), e0b = mul2(tb, tb);
                A20 = fma2(wj, e2a, A20); A10 = fma2(wj, e1a, A10); A00 = fma2(wj, e0a, A00);
                A21 = fma2(wj, e2b, A21); A11 = fma2(wj, e1b, A11); A01 = fma2(wj, e0b, A01);
            }
        }
        float l, h;
        unpack2(A00, l, h); r00 = l + h;
        unpack2(A10, l, h); r10 = l + h;
        unpack2(A20, l, h); r20 = l + h;
        unpack2(A01, l, h); r01 = l + h;
        unpack2(A11, l, h); r11 = l + h;
        unpack2(A21, l, h); r21 = l + h;
        unpack2(SD,  l, h); sds = l + h;
    } else {
        // generic fallback
        r00 = r10 = r20 = r01 = r11 = r21 = 0.f;
        for (int j = 0; j < TILE; j++) {
            float xj = s_x[j], yj = s_y[j], w = s_w[j];
            float dx0 = x0 - xj, dy0 = y0 - yj;
            float dx1 = x1 - xj, dy1 = y1 - yj;
            if (mat == 2) {
                float d2r0 = fmaf(dx0, dx0, dy0 * dy0);
                float d2r1 = fmaf(dx1, dx1, dy1 * dy1);
                sds += sqrtap(d2r0) + sqrtap(d2r1);
                dx0 -= delx; dy0 -= dely; dx1 -= delx; dy1 -= dely;
            }
            float d20 = fmaf(dx0, dx0, dy0 * dy0);
            float d21 = fmaf(dx1, dx1, dy1 * dy1);
            r00 = fmaf(w, ex2f(m0 * d20), r00);
            r10 = fmaf(w, ex2f(m1 * d20), r10);
            r20 = fmaf(w, ex2f(m2 * d20), r20);
            r01 = fmaf(w, ex2f(m0 * d21), r01);
            r11 = fmaf(w, ex2f(m1 * d21), r11);
            r21 = fmaf(w, ex2f(m2 * d21), r21);
        }
    }

    float f = (mat != 2 && ti != tj) ? 2.f : 1.f;
    float w0 = f * u0, w1v = f * u1;
    float a0s = fmaf(w0, r00, w1v * r01);
    float a1s = fmaf(w0, r10, w1v * r11);
    float a2s = fmaf(w0, r20, w1v * r21);

    float r;
    r = block_reduce<4>(a0s, sred); if (tid == 0) atomicAdd(&g_pacc[mat * 3 + 0], (double)r);
    r = block_reduce<4>(a1s, sred); if (tid == 0) atomicAdd(&g_pacc[mat * 3 + 1], (double)r);
    r = block_reduce<4>(a2s, sred); if (tid == 0) atomicAdd(&g_pacc[mat * 3 + 2], (double)r);
    if (mat == 2) {
        r = block_reduce<4>(sds, sred); if (tid == 0) atomicAdd(&g_pacc[9], (double)r);
    }

    // ---- last block finalizes (replaces k_final launch) ----
    if (tid == 0) {
        __threadfence();
        unsigned old = atomicAdd(&g_ctr[1], 1u);
        slast = (old == NBLK - 1);
    }
    __syncthreads();
    if (slast && tid < 32) {
        __threadfence();
        int lane = tid;
        double Ub = ldv(&g_wacc[0]), U2b = ldv(&g_wacc[1]);
        double Ut = ldv(&g_wacc[7]), U2t = ldv(&g_wacc[8]);
        const double n = (double)N_PTS;
        const double invNM  = 1.0 / (67108864.0);       // 1/N^2 (exact 2^-26)
        const double invNM1 = 1.0 / (67108863.0);       // 1/(N^2-1)
        const double invn1  = 1.0 / 8191.0;

        double sum_d2 = n * (ldv(&g_wacc[6]) + ldv(&g_wacc[13]))
                      - 2.0 * (ldv(&g_wacc[4]) * ldv(&g_wacc[11])
                             + ldv(&g_wacc[5]) * ldv(&g_wacc[12]));
        double sd = ldv(&g_pacc[9]);
        double meand = sd * invNM;
        double vard  = (sum_d2 - sd * sd * invNM) * invNM1;

        double iUb = frcp(Ub), iUt = frcp(Ut);
        double iUb2 = iUb * iUb, iUt2 = iUt * iUt, iUbt = iUb * iUt;
        double wvar = (U2b * iUb2 - 1.0 / n) * invn1
                    + (U2t * iUt2 - 1.0 / n) * invn1;

        float stats[4] = { (float)meand, (float)vard, 0.f, (float)wvar };

        float L[3];
        #pragma unroll
        for (int k = 0; k < 3; k++)
            L[k] = (float)(ldv(&g_pacc[k]) * iUb2 + ldv(&g_pacc[3 + k]) * iUt2
                         - 2.0 * ldv(&g_pacc[6 + k]) * iUbt);

        float v = gb1[lane];
        #pragma unroll
        for (int d = 0; d < 4; d++) v = fmaf(stats[d], gw1[d * 32 + lane], v);
        float hrel = fmaxf(v, 0.f);

        float g[3], gs = 0.f;
        #pragma unroll
        for (int s = 0; s < 3; s++) {
            float p = hrel * gw2[lane * 3 + s];
            #pragma unroll
            for (int o = 16; o > 0; o >>= 1) p += __shfl_xor_sync(0xffffffffu, p, o);
            p += gb2[s];
            float sp = (p > 15.f) ? p : log1pf(__expf(p));
            g[s] = sp; gs += sp;
        }
        if (lane == 0) {
            float res = bias[0];
            float rgs = 1.f / gs;
            #pragma unroll
            for (int s = 0; s < 3; s++) res = fmaf(g[s] * rgs, L[s], res);
            out[0] = res;
        }
    }
}

// ---------------- launch ------------------------------------------------
extern "C" void kernel_launch(void* const* d_in, const int* in_sizes, int n_in,
                              void* d_out, int out_size)
{
    const float* base       = (const float*)d_in[0];
    const float* target     = (const float*)d_in[1];
    const float* log_sigmas = (const float*)d_in[2];
    const float* log_scale  = (const float*)d_in[3];
    const float* wn_w1      = (const float*)d_in[4];
    const float* wn_b1      = (const float*)d_in[5];
    const float* wn_w2      = (const float*)d_in[6];
    const float* wn_b2      = (const float*)d_in[7];
    const float* g_w1       = (const float*)d_in[8];
    const float* g_b1       = (const float*)d_in[9];
    const float* g_w2       = (const float*)d_in[10];
    const float* g_b2       = (const float*)d_in[11];
    const float* bias       = (const float*)d_in[12];

    k_init<<<1, 32>>>();
    k_weights<<<64, 256>>>(base, target, log_scale, log_sigmas,
                           wn_w1, wn_b1, wn_w2, wn_b2);
    k_pairs<<<NBLK, 128>>>(g_w1, g_b1, g_w2, g_b2, bias, (float*)d_out);
}

// round 8
// speedup vs baseline: 1.3541x; 1.0734x over previous
#include <cuda_runtime.h>
#include <math.h>

#define N_PTS 8192
#define TILE  256
#define NT    32
#define NTRI  528        // NT*(NT+1)/2
#define NBLK  2080       // 2*NTRI + NT*NT
#define NWB   128        // blocks that also do weight duty (must be <= 148)

typedef unsigned long long u64;

// ---------------- packed f32x2 helpers (sm_100+) ------------------------
static __device__ __forceinline__ u64 pack2(float lo, float hi) {
    u64 r; asm("mov.b64 %0, {%1, %2};" : "=l"(r) : "f"(lo), "f"(hi)); return r;
}
static __device__ __forceinline__ void unpack2(u64 v, float& lo, float& hi) {
    asm("mov.b64 {%0, %1}, %2;" : "=f"(lo), "=f"(hi) : "l"(v));
}
static __device__ __forceinline__ u64 fma2(u64 a, u64 b, u64 c) {
    u64 r; asm("fma.rn.f32x2 %0, %1, %2, %3;" : "=l"(r) : "l"(a), "l"(b), "l"(c)); return r;
}
static __device__ __forceinline__ u64 mul2(u64 a, u64 b) {
    u64 r; asm("mul.rn.f32x2 %0, %1, %2;" : "=l"(r) : "l"(a), "l"(b)); return r;
}
static __device__ __forceinline__ u64 add2(u64 a, u64 b) {
    u64 r; asm("add.rn.f32x2 %0, %1, %2;" : "=l"(r) : "l"(a), "l"(b)); return r;
}
static __device__ __forceinline__ u64 sub2(u64 a, u64 b) {
    u64 r; asm("sub.rn.f32x2 %0, %1, %2;" : "=l"(r) : "l"(a), "l"(b)); return r;
}
static __device__ __forceinline__ float ex2f(float x) {
    float r; asm("ex2.approx.ftz.f32 %0, %1;" : "=f"(r) : "f"(x)); return r;
}
static __device__ __forceinline__ float sqrtap(float x) {
    float r; asm("sqrt.approx.f32 %0, %1;" : "=f"(r) : "f"(x)); return r;
}
// fast double reciprocal: float RCP seed + 2 Newton steps (~1e-16 rel)
static __device__ __forceinline__ double frcp(double x) {
    float rf; asm("rcp.approx.f32 %0, %1;" : "=f"(rf) : "f"((float)x));
    double r = (double)rf;
    r = r * (2.0 - x * r);
    r = r * (2.0 - x * r);
    return r;
}
static __device__ __forceinline__ double ldv(const double* p) {
    return *(volatile const double*)p;
}
static __device__ __forceinline__ unsigned ld_acq(const unsigned* p) {
    unsigned v; asm volatile("ld.acquire.gpu.u32 %0, [%1];" : "=r"(v) : "l"(p) : "memory");
    return v;
}

// ---------------- device scratch (zero at load; finalize re-zeroes) -----
// per cloud c (0=base,1=target), offset o=c*7:
//   o+0: sum u, o+1: sum u^2, o+2: sum u*x, o+3: sum u*y,
//   o+4: sum x, o+5: sum y,   o+6: sum (x^2+y^2)
__device__ double g_wacc[14];
// 0..2 = S_aa bands, 3..5 = S_bb, 6..8 = S_ab, 9 = sum dist (half-sampled x2)
__device__ double g_pacc[10];
__device__ float g_px[2][N_PTS];
__device__ float g_py[2][N_PTS];
__device__ float g_u[2][N_PTS];
// uniforms: 0:delx 1:dely 2:m0 3:m1 4:m2 5:fast 6:del2
__device__ float g_cc[8];
__device__ unsigned g_ctr[2];
__device__ unsigned g_flag;

// valid on thread 0; blockDim 128 (4 warps)
static __device__ __forceinline__ float block_reduce(float v, float* sbuf) {
    __syncthreads();
    #pragma unroll
    for (int o = 16; o > 0; o >>= 1) v += __shfl_down_sync(0xffffffffu, v, o);
    int warp = threadIdx.x >> 5, lane = threadIdx.x & 31;
    if (lane == 0) sbuf[warp] = v;
    __syncthreads();
    if (warp == 0) {
        v = (lane < 4) ? sbuf[lane] : 0.f;
        v += __shfl_down_sync(0xffffffffu, v, 2);
        v += __shfl_down_sync(0xffffffffu, v, 1);
    }
    return v;
}

// ---------------- single fused kernel ----------------------------------
__global__ __launch_bounds__(128) void k_fused(
    const float* __restrict__ base, const float* __restrict__ target,
    const float* __restrict__ log_scale, const float* __restrict__ log_sigmas,
    const float* __restrict__ w1, const float* __restrict__ b1,
    const float* __restrict__ w2, const float* __restrict__ b2,
    const float* __restrict__ gw1, const float* __restrict__ gb1,
    const float* __restrict__ gw2, const float* __restrict__ gb2,
    const float* __restrict__ bias, float* __restrict__ out)
{
    __shared__ alignas(8) float s_x[TILE];
    __shared__ alignas(8) float s_y[TILE];
    __shared__ alignas(8) float s_q[TILE];
    __shared__ alignas(8) float s_w[TILE];
    __shared__ float sred[4];
    __shared__ int slast;
    if (threadIdx.x == 0) slast = 0;

    int b = blockIdx.x;
    int tid = threadIdx.x;

    // ============ phase 1: weight MLP + moments (blocks 0..NWB-1) =======
    if (b < NWB) {
        int cloud = b >> 6;                       // 64 blocks per cloud
        int idx   = ((b & 63) << 7) + tid;        // 128 points per block
        const float* pts = cloud ? target : base;

        float sx = expf(log_scale[0]);
        float sy = expf(log_scale[1]);
        float x = pts[2 * idx]     * sx;
        float y = pts[2 * idx + 1] * sy;

        float logit = b2[0];
        #pragma unroll
        for (int j = 0; j < 32; j++) {
            float h = fmaf(x, w1[j], fmaf(y, w1[32 + j], b1[j]));
            h = fmaxf(h, 0.f);
            logit = fmaf(h, w2[j], logit);
        }
        float sp = (logit > 15.f) ? logit : log1pf(__expf(logit));
        float u = sp + 1e-6f;

        g_px[cloud][idx] = x;
        g_py[cloud][idx] = y;
        g_u[cloud][idx]  = u;

        int o = cloud * 7;
        float r;
        r = block_reduce(u,             sred); if (tid == 0) atomicAdd(&g_wacc[o + 0], (double)r);
        r = block_reduce(u * u,         sred); if (tid == 0) atomicAdd(&g_wacc[o + 1], (double)r);
        r = block_reduce(u * x,         sred); if (tid == 0) atomicAdd(&g_wacc[o + 2], (double)r);
        r = block_reduce(u * y,         sred); if (tid == 0) atomicAdd(&g_wacc[o + 3], (double)r);
        r = block_reduce(x,             sred); if (tid == 0) atomicAdd(&g_wacc[o + 4], (double)r);
        r = block_reduce(y,             sred); if (tid == 0) atomicAdd(&g_wacc[o + 5], (double)r);
        r = block_reduce(fmaf(x,x,y*y), sred); if (tid == 0) atomicAdd(&g_wacc[o + 6], (double)r);

        if (tid == 0) {
            __threadfence();
            unsigned old = atomicAdd(&g_ctr[0], 1u);
            if (old == NWB - 1) {
                // all weight contributions visible (atomic chain on g_ctr[0])
                __threadfence();
                double Ub  = ldv(&g_wacc[0]), Ut = ldv(&g_wacc[7]);
                double iUb = frcp(Ub), iUt = frcp(Ut);
                float delx = (float)(ldv(&g_wacc[2]) * iUb - ldv(&g_wacc[9])  * iUt);
                float dely = (float)(ldv(&g_wacc[3]) * iUb - ldv(&g_wacc[10]) * iUt);
                const float L2E = 1.4426950408889634f;
                float s0 = expf(log_sigmas[0]);
                float s1 = expf(log_sigmas[1]);
                float s2 = expf(log_sigmas[2]);
                float m0 = -L2E / (2.f * s0 * s0);
                float m1 = -L2E / (2.f * s1 * s1);
                float m2 = -L2E / (2.f * s2 * s2);
                bool fastok = (fabsf(m1 / m2 - 4.f) < 4e-4f) && (fabsf(m0 / m2 - 16.f) < 1.6e-3f);
                g_cc[0] = delx; g_cc[1] = dely;
                g_cc[2] = m0;   g_cc[3] = m1;   g_cc[4] = m2;
                g_cc[5] = fastok ? 1.f : 0.f;
                g_cc[6] = delx * delx + dely * dely;
                __threadfence();
                atomicExch(&g_flag, 1u);   // release
            }
        }
    }

    // ============ wait for uniforms (every thread acquires) =============
    while (ld_acq(&g_flag) == 0u) __nanosleep(64);

    // ============ phase 2: pairwise tile ================================
    // decode block: interleave tri / full tiles for pipe balance
    int mat, ti, tj;
    int t = -1;
    if (b < 2048) {
        if (b & 1) { int f = b >> 1; mat = 2; ti = f >> 5; tj = f & 31; }
        else t = b >> 1;
    } else t = 1024 + (b - 2048);
    if (t >= 0) {
        mat = (t < NTRI) ? 0 : 1;
        if (t >= NTRI) t -= NTRI;
        int r = 0;
        while (t >= NT - r) { t -= NT - r; r++; }
        ti = r; tj = r + t;
    }

    float m0 = g_cc[2], m1 = g_cc[3], m2 = g_cc[4];
    bool fast = (g_cc[5] != 0.f);
    float delx = g_cc[0], dely = g_cc[1], del2 = g_cc[6];

    int ci_cloud = (mat == 1) ? 1 : 0;
    int cj_cloud = (mat == 0) ? 0 : 1;

    #pragma unroll
    for (int tt = tid; tt < TILE; tt += 128) {
        int j = (tj << 8) + tt;
        float xj = g_px[cj_cloud][j], yj = g_py[cj_cloud][j];
        s_x[tt] = xj; s_y[tt] = yj;
        s_w[tt] = g_u[cj_cloud][j];
        s_q[tt] = (mat == 2) ? 2.f * (delx * xj + dely * yj)
                             : m2 * fmaf(xj, xj, yj * yj);
    }
    __syncthreads();

    // two i rows per thread
    int i0 = (ti << 8) + tid, i1 = i0 + 128;
    float x0 = g_px[ci_cloud][i0], y0 = g_py[ci_cloud][i0], u0 = g_u[ci_cloud][i0];
    float x1 = g_px[ci_cloud][i1], y1 = g_py[ci_cloud][i1], u1 = g_u[ci_cloud][i1];

    float r00, r10, r20, r01, r11, r21, sds = 0.f;

    if (fast) {
        u64 A00 = 0, A10 = 0, A20 = 0, A01 = 0, A11 = 0, A21 = 0, SD = 0;
        if (mat != 2) {
            float q0 = m2 * fmaf(x0, x0, y0 * y0);
            float q1 = m2 * fmaf(x1, x1, y1 * y1);
            u64 X20 = pack2(-2.f * m2 * x0, -2.f * m2 * x0);
            u64 Y20 = pack2(-2.f * m2 * y0, -2.f * m2 * y0);
            u64 QI0 = pack2(q0, q0);
            u64 X21 = pack2(-2.f * m2 * x1, -2.f * m2 * x1);
            u64 Y21 = pack2(-2.f * m2 * y1, -2.f * m2 * y1);
            u64 QI1 = pack2(q1, q1);
            #pragma unroll 4
            for (int j = 0; j < TILE; j += 2) {
                u64 xj = *(const u64*)&s_x[j];
                u64 yj = *(const u64*)&s_y[j];
                u64 qj = *(const u64*)&s_q[j];
                u64 wj = *(const u64*)&s_w[j];
                u64 arg0 = add2(fma2(X20, xj, fma2(Y20, yj, qj)), QI0);
                u64 arg1 = add2(fma2(X21, xj, fma2(Y21, yj, qj)), QI1);
                float l0, h0, l1, h1;
                unpack2(arg0, l0, h0); unpack2(arg1, l1, h1);
                u64 e2a = pack2(ex2f(l0), ex2f(h0));
                u64 e2b = pack2(ex2f(l1), ex2f(h1));
                u64 sa = mul2(e2a, e2a), e1a = mul2(sa, sa);
                u64 ta = mul2(e1a, e1a), e0a = mul2(ta, ta);
                u64 sb = mul2(e2b, e2b), e1b = mul2(sb, sb);
                u64 tb = mul2(e1b, e1b), e0b = mul2(tb, tb);
                A20 = fma2(wj, e2a, A20); A10 = fma2(wj, e1a, A10); A00 = fma2(wj, e0a, A00);
                A21 = fma2(wj, e2b, A21); A11 = fma2(wj, e1b, A11); A01 = fma2(wj, e0b, A01);
            }
        } else {
            float c0 = m2 * (del2 - 2.f * (delx * x0 + dely * y0));
            float c1 = m2 * (del2 - 2.f * (delx * x1 + dely * y1));
            u64 PX0 = pack2(x0, x0), PY0 = pack2(y0, y0), CI0 = pack2(c0, c0);
            u64 PX1 = pack2(x1, x1), PY1 = pack2(y1, y1), CI1 = pack2(c1, c1);
            u64 M2 = pack2(m2, m2);
            // sqrt-stat half-sampling: accumulate sqrt only for j%4 in {0,1}; x2 later
            #pragma unroll 2
            for (int j = 0; j < TILE; j += 4) {
                // --- packed pair (j, j+1): with sqrt stats ---
                {
                    u64 xj = *(const u64*)&s_x[j];
                    u64 yj = *(const u64*)&s_y[j];
                    u64 kj = *(const u64*)&s_q[j];
                    u64 wj = *(const u64*)&s_w[j];
                    u64 dx0 = sub2(PX0, xj), dy0 = sub2(PY0, yj);
                    u64 d2r0 = fma2(dx0, dx0, mul2(dy0, dy0));
                    float dl0, dh0; unpack2(d2r0, dl0, dh0);
                    SD = add2(SD, pack2(sqrtap(dl0), sqrtap(dh0)));
                    u64 arg0 = fma2(add2(d2r0, kj), M2, CI0);
                    u64 dx1 = sub2(PX1, xj), dy1 = sub2(PY1, yj);
                    u64 d2r1 = fma2(dx1, dx1, mul2(dy1, dy1));
                    float dl1, dh1; unpack2(d2r1, dl1, dh1);
                    SD = add2(SD, pack2(sqrtap(dl1), sqrtap(dh1)));
                    u64 arg1 = fma2(add2(d2r1, kj), M2, CI1);
                    float l0, h0, l1, h1;
                    unpack2(arg0, l0, h0); unpack2(arg1, l1, h1);
                    u64 e2a = pack2(ex2f(l0), ex2f(h0));
                    u64 e2b = pack2(ex2f(l1), ex2f(h1));
                    u64 sa = mul2(e2a, e2a), e1a = mul2(sa, sa);
                    u64 ta = mul2(e1a, e1a), e0a = mul2(ta, ta);
                    u64 sb = mul2(e2b, e2b), e1b = mul2(sb, sb);
                    u64 tb = mul2(e1b, e1b), e0b = mul2(tb, tb);
                    A20 = fma2(wj, e2a, A20); A10 = fma2(wj, e1a, A10); A00 = fma2(wj, e0a, A00);
                    A21 = fma2(wj, e2b, A21); A11 = fma2(wj, e1b, A11); A01 = fma2(wj, e0b, A01);
                }
                // --- packed pair (j+2, j+3): no sqrt stats ---
                {
                    u64 xj = *(const u64*)&s_x[j + 2];
                    u64 yj = *(const u64*)&s_y[j + 2];
                    u64 kj = *(const u64*)&s_q[j + 2];
                    u64 wj = *(const u64*)&s_w[j + 2];
                    u64 dx0 = sub2(PX0, xj), dy0 = sub2(PY0, yj);
                    u64 d2r0 = fma2(dx0, dx0, mul2(dy0, dy0));
                    u64 arg0 = fma2(add2(d2r0, kj), M2, CI0);
                    u64 dx1 = sub2(PX1, xj), dy1 = sub2(PY1, yj);
                    u64 d2r1 = fma2(dx1, dx1, mul2(dy1, dy1));
                    u64 arg1 = fma2(add2(d2r1, kj), M2, CI1);
                    float l0, h0, l1, h1;
                    unpack2(arg0, l0, h0); unpack2(arg1, l1, h1);
                    u64 e2a = pack2(ex2f(l0), ex2f(h0));
                    u64 e2b = pack2(ex2f(l1), ex2f(h1));
                    u64 sa = mul2(e2a, e2a), e1a = mul2(sa, sa);
                    u64 ta = mul2(e1a, e1a), e0a = mul2(ta, ta);
                    u64 sb = mul2(e2b, e2b), e1b = mul2(sb, sb);
                    u64 tb = mul2(e1b, e1b), e0b = mul2(tb, tb);
                    A20 = fma2(wj, e2a, A20); A10 = fma2(wj, e1a, A10); A00 = fma2(wj, e0a, A00);
                    A21 = fma2(wj, e2b, A21); A11 = fma2(wj, e1b, A11); A01 = fma2(wj, e0b, A01);
                }
            }
        }
        float l, h;
        unpack2(A00, l, h); r00 = l + h;
        unpack2(A10, l, h); r10 = l + h;
        unpack2(A20, l, h); r20 = l + h;
        unpack2(A01, l, h); r01 = l + h;
        unpack2(A11, l, h); r11 = l + h;
        unpack2(A21, l, h); r21 = l + h;
        unpack2(SD,  l, h); sds = l + h;
    } else {
        // generic fallback (full sqrt sampling; scaled by 0.5 to match x2 below)
        r00 = r10 = r20 = r01 = r11 = r21 = 0.f;
        float sdfull = 0.f;
        for (int j = 0; j < TILE; j++) {
            float xj = s_x[j], yj = s_y[j], w = s_w[j];
            float dx0 = x0 - xj, dy0 = y0 - yj;
            float dx1 = x1 - xj, dy1 = y1 - yj;
            if (mat == 2) {
                float d2r0 = fmaf(dx0, dx0, dy0 * dy0);
                float d2r1 = fmaf(dx1, dx1, dy1 * dy1);
                sdful1: ;
                sdfull += sqrtap(d2r0) + sqrtap(d2r1);
                dx0 -= delx; dy0 -= dely; dx1 -= delx; dy1 -= dely;
            }
            float d20 = fmaf(dx0, dx0, dy0 * dy0);
            float d21 = fmaf(dx1, dx1, dy1 * dy1);
            r00 = fmaf(w, ex2f(m0 * d20), r00);
            r10 = fmaf(w, ex2f(m1 * d20), r10);
            r20 = fmaf(w, ex2f(m2 * d20), r20);
            r01 = fmaf(w, ex2f(m0 * d21), r01);
            r11 = fmaf(w, ex2f(m1 * d21), r11);
            r21 = fmaf(w, ex2f(m2 * d21), r21);
        }
        sds = 0.5f * sdfull;   // finalize applies x2
    }

    float f = (mat != 2 && ti != tj) ? 2.f : 1.f;
    float w0 = f * u0, w1v = f * u1;
    float a0s = fmaf(w0, r00, w1v * r01);
    float a1s = fmaf(w0, r10, w1v * r11);
    float a2s = fmaf(w0, r20, w1v * r21);

    float r;
    r = block_reduce(a0s, sred); if (tid == 0) atomicAdd(&g_pacc[mat * 3 + 0], (double)r);
    r = block_reduce(a1s, sred); if (tid == 0) atomicAdd(&g_pacc[mat * 3 + 1], (double)r);
    r = block_reduce(a2s, sred); if (tid == 0) atomicAdd(&g_pacc[mat * 3 + 2], (double)r);
    if (mat == 2) {
        r = block_reduce(2.f * sds, sred);      // x2: half-sampled sqrt subset
        if (tid == 0) atomicAdd(&g_pacc[9], (double)r);
    }

    // ============ last block finalizes + re-zeroes state ================
    if (tid == 0) {
        __threadfence();
        unsigned old = atomicAdd(&g_ctr[1], 1u);
        slast = (old == NBLK - 1);
    }
    __syncthreads();
    if (slast && tid < 32) {
        __threadfence();
        int lane = tid;
        double Ub = ldv(&g_wacc[0]), U2b = ldv(&g_wacc[1]);
        double Ut = ldv(&g_wacc[7]), U2t = ldv(&g_wacc[8]);
        const double n = (double)N_PTS;
        const double invNM  = 1.0 / 67108864.0;   // 1/N^2
        const double invNM1 = 1.0 / 67108863.0;   // 1/(N^2-1)
        const double invn1  = 1.0 / 8191.0;

        double sum_d2 = n * (ldv(&g_wacc[6]) + ldv(&g_wacc[13]))
                      - 2.0 * (ldv(&g_wacc[4]) * ldv(&g_wacc[11])
                             + ldv(&g_wacc[5]) * ldv(&g_wacc[12]));
        double sd = ldv(&g_pacc[9]);
        double meand = sd * invNM;
        double vard  = (sum_d2 - sd * sd * invNM) * invNM1;

        double iUb = frcp(Ub), iUt = frcp(Ut);
        double iUb2 = iUb * iUb, iUt2 = iUt * iUt, iUbt = iUb * iUt;
        double wvar = (U2b * iUb2 - 1.0 / n) * invn1
                    + (U2t * iUt2 - 1.0 / n) * invn1;

        float stats[4] = { (float)meand, (float)vard, 0.f, (float)wvar };

        float L[3];
        #pragma unroll
        for (int k = 0; k < 3; k++)
            L[k] = (float)(ldv(&g_pacc[k]) * iUb2 + ldv(&g_pacc[3 + k]) * iUt2
                         - 2.0 * ldv(&g_pacc[6 + k]) * iUbt);

        float v = gb1[lane];
        #pragma unroll
        for (int d = 0; d < 4; d++) v = fmaf(stats[d], gw1[d * 32 + lane], v);
        float hrel = fmaxf(v, 0.f);

        float g[3], gs = 0.f;
        #pragma unroll
        for (int s = 0; s < 3; s++) {
            float p = hrel * gw2[lane * 3 + s];
            #pragma unroll
            for (int o = 16; o > 0; o >>= 1) p += __shfl_xor_sync(0xffffffffu, p, o);
            p += gb2[s];
            float sp = (p > 15.f) ? p : log1pf(__expf(p));
            g[s] = sp; gs += sp;
        }
        if (lane == 0) {
            float res = bias[0];
            float rgs = 1.f / gs;
            #pragma unroll
            for (int s = 0; s < 3; s++) res = fmaf(g[s] * rgs, L[s], res);
            out[0] = res;
        }

        // re-zero all device state so the next graph replay starts clean
        __syncwarp();
        if (lane < 14) *(volatile double*)&g_wacc[lane] = 0.0;
        if (lane < 10) *(volatile double*)&g_pacc[lane] = 0.0;
        if (lane < 2)  *(volatile unsigned*)&g_ctr[lane] = 0u;
        if (lane == 0) { __threadfence(); atomicExch(&g_flag, 0u); }
    }
}

// ---------------- launch ------------------------------------------------
extern "C" void kernel_launch(void* const* d_in, const int* in_sizes, int n_in,
                              void* d_out, int out_size)
{
    const float* base       = (const float*)d_in[0];
    const float* target     = (const float*)d_in[1];
    const float* log_sigmas = (const float*)d_in[2];
    const float* log_scale  = (const float*)d_in[3];
    const float* wn_w1      = (const float*)d_in[4];
    const float* wn_b1      = (const float*)d_in[5];
    const float* wn_w2      = (const float*)d_in[6];
    const float* wn_b2      = (const float*)d_in[7];
    const float* g_w1       = (const float*)d_in[8];
    const float* g_b1       = (const float*)d_in[9];
    const float* g_w2       = (const float*)d_in[10];
    const float* g_b2       = (const float*)d_in[11];
    const float* bias       = (const float*)d_in[12];

    k_fused<<<NBLK, 128>>>(base, target, log_scale, log_sigmas,
                           wn_w1, wn_b1, wn_w2, wn_b2,
                           g_w1, g_b1, g_w2, g_b2, bias, (float*)d_out);
}

// round 9
// speedup vs baseline: 1.4398x; 1.0633x over previous
#include <cuda_runtime.h>
#include <math.h>

#define N_PTS 8192
#define TILE  256
#define NT    32
#define NTRI  528        // NT*(NT+1)/2
#define NBLK  2080       // 2*NTRI + NT*NT
#define NWB   128        // weight-duty blocks (<= wave 1)

typedef unsigned long long u64;

// ---------------- packed f32x2 helpers (sm_100+) ------------------------
static __device__ __forceinline__ u64 pack2(float lo, float hi) {
    u64 r; asm("mov.b64 %0, {%1, %2};" : "=l"(r) : "f"(lo), "f"(hi)); return r;
}
static __device__ __forceinline__ void unpack2(u64 v, float& lo, float& hi) {
    asm("mov.b64 {%0, %1}, %2;" : "=f"(lo), "=f"(hi) : "l"(v));
}
static __device__ __forceinline__ u64 fma2(u64 a, u64 b, u64 c) {
    u64 r; asm("fma.rn.f32x2 %0, %1, %2, %3;" : "=l"(r) : "l"(a), "l"(b), "l"(c)); return r;
}
static __device__ __forceinline__ u64 mul2(u64 a, u64 b) {
    u64 r; asm("mul.rn.f32x2 %0, %1, %2;" : "=l"(r) : "l"(a), "l"(b)); return r;
}
static __device__ __forceinline__ u64 add2(u64 a, u64 b) {
    u64 r; asm("add.rn.f32x2 %0, %1, %2;" : "=l"(r) : "l"(a), "l"(b)); return r;
}
static __device__ __forceinline__ u64 sub2(u64 a, u64 b) {
    u64 r; asm("sub.rn.f32x2 %0, %1, %2;" : "=l"(r) : "l"(a), "l"(b)); return r;
}
static __device__ __forceinline__ float ex2f(float x) {
    float r; asm("ex2.approx.ftz.f32 %0, %1;" : "=f"(r) : "f"(x)); return r;
}
static __device__ __forceinline__ float sqrtap(float x) {
    float r; asm("sqrt.approx.f32 %0, %1;" : "=f"(r) : "f"(x)); return r;
}
static __device__ __forceinline__ double frcp(double x) {
    float rf; asm("rcp.approx.f32 %0, %1;" : "=f"(rf) : "f"((float)x));
    double r = (double)rf;
    r = r * (2.0 - x * r);
    r = r * (2.0 - x * r);
    return r;
}
static __device__ __forceinline__ double ldv(const double* p) {
    return *(volatile const double*)p;
}
static __device__ __forceinline__ unsigned ld_acq(const unsigned* p) {
    unsigned v; asm volatile("ld.acquire.gpu.u32 %0, [%1];" : "=r"(v) : "l"(p) : "memory");
    return v;
}

// exp2 of both lanes of a packed reg
#define EX2P(dst, src) { float _l, _h; unpack2(src, _l, _h); dst = pack2(ex2f(_l), ex2f(_h)); }
// band power chain + accumulate: e1 = e2^4, e0 = e2^16
#define CHAIN(e2v, wv, A2v, A1v, A0v) { \
    u64 _s = mul2(e2v, e2v); u64 _e1 = mul2(_s, _s); \
    u64 _t = mul2(_e1, _e1); u64 _e0 = mul2(_t, _t); \
    A2v = fma2(wv, e2v, A2v); A1v = fma2(wv, _e1, A1v); A0v = fma2(wv, _e0, A0v); }

// ---------------- device scratch (zero at load; finalize re-zeroes) -----
__device__ double g_wacc[14];   // per cloud c: o=c*7: sum u,u^2,ux,uy,x,y,(x^2+y^2)
__device__ double g_pacc[10];   // 0..2 aa, 3..5 bb, 6..8 ab, 9 sum dist (half x2)
__device__ float g_px[2][N_PTS];
__device__ float g_py[2][N_PTS];
__device__ float g_u[2][N_PTS];
__device__ float g_cc[2];       // delx, dely
__device__ unsigned g_ctr[2];
__device__ unsigned g_flag;

// valid on thread 0; blockDim 128 (4 warps)
static __device__ __forceinline__ float block_reduce(float v, float* sbuf) {
    __syncthreads();
    #pragma unroll
    for (int o = 16; o > 0; o >>= 1) v += __shfl_down_sync(0xffffffffu, v, o);
    int warp = threadIdx.x >> 5, lane = threadIdx.x & 31;
    if (lane == 0) sbuf[warp] = v;
    __syncthreads();
    if (warp == 0) {
        v = (lane < 4) ? sbuf[lane] : 0.f;
        v += __shfl_down_sync(0xffffffffu, v, 2);
        v += __shfl_down_sync(0xffffffffu, v, 1);
    }
    return v;
}

// scale + weight-net MLP for one point (deterministic; identical to phase 1)
static __device__ __forceinline__ void mlp_xyu(
    const float* __restrict__ pts, int idx, float sx, float sy,
    const float* __restrict__ w1, const float* __restrict__ b1,
    const float* __restrict__ w2, const float* __restrict__ b2,
    float& x, float& y, float& u)
{
    x = pts[2 * idx]     * sx;
    y = pts[2 * idx + 1] * sy;
    float logit = b2[0];
    #pragma unroll
    for (int j = 0; j < 32; j++) {
        float h = fmaf(x, w1[j], fmaf(y, w1[32 + j], b1[j]));
        h = fmaxf(h, 0.f);
        logit = fmaf(h, w2[j], logit);
    }
    float sp = (logit > 15.f) ? logit : log1pf(__expf(logit));
    u = sp + 1e-6f;
}

// ---------------- single fused kernel ----------------------------------
__global__ __launch_bounds__(128) void k_fused(
    const float* __restrict__ base, const float* __restrict__ target,
    const float* __restrict__ log_scale, const float* __restrict__ log_sigmas,
    const float* __restrict__ w1, const float* __restrict__ b1,
    const float* __restrict__ w2, const float* __restrict__ b2,
    const float* __restrict__ gw1, const float* __restrict__ gb1,
    const float* __restrict__ gw2, const float* __restrict__ gb2,
    const float* __restrict__ bias, float* __restrict__ out)
{
    __shared__ alignas(8) float s_x[TILE];
    __shared__ alignas(8) float s_y[TILE];
    __shared__ alignas(8) float s_q[TILE];
    __shared__ alignas(8) float s_w[TILE];
    __shared__ float sred[4];
    __shared__ int slast;
    if (threadIdx.x == 0) slast = 0;

    int b = blockIdx.x;
    int tid = threadIdx.x;

    // local uniforms (no global dependency)
    float sx = expf(log_scale[0]);
    float sy = expf(log_scale[1]);
    const float L2E = 1.4426950408889634f;
    float s0e = expf(log_sigmas[0]);
    float s1e = expf(log_sigmas[1]);
    float s2e = expf(log_sigmas[2]);
    float m0 = -L2E / (2.f * s0e * s0e);
    float m1 = -L2E / (2.f * s1e * s1e);
    float m2 = -L2E / (2.f * s2e * s2e);
    bool fast = (fabsf(m1 / m2 - 4.f) < 4e-4f) && (fabsf(m0 / m2 - 16.f) < 1.6e-3f);

    // ============ phase 1: weight MLP + moments (blocks 0..NWB-1) =======
    if (b < NWB) {
        int cloud = b >> 6;
        int idx   = ((b & 63) << 7) + tid;
        const float* pts = cloud ? target : base;
        float x, y, u;
        mlp_xyu(pts, idx, sx, sy, w1, b1, w2, b2, x, y, u);

        g_px[cloud][idx] = x;
        g_py[cloud][idx] = y;
        g_u[cloud][idx]  = u;

        int o = cloud * 7;
        float r;
        r = block_reduce(u,             sred); if (tid == 0) atomicAdd(&g_wacc[o + 0], (double)r);
        r = block_reduce(u * u,         sred); if (tid == 0) atomicAdd(&g_wacc[o + 1], (double)r);
        r = block_reduce(u * x,         sred); if (tid == 0) atomicAdd(&g_wacc[o + 2], (double)r);
        r = block_reduce(u * y,         sred); if (tid == 0) atomicAdd(&g_wacc[o + 3], (double)r);
        r = block_reduce(x,             sred); if (tid == 0) atomicAdd(&g_wacc[o + 4], (double)r);
        r = block_reduce(y,             sred); if (tid == 0) atomicAdd(&g_wacc[o + 5], (double)r);
        r = block_reduce(fmaf(x,x,y*y), sred); if (tid == 0) atomicAdd(&g_wacc[o + 6], (double)r);

        if (tid == 0) {
            __threadfence();
            unsigned old = atomicAdd(&g_ctr[0], 1u);
            if (old == NWB - 1) {
                __threadfence();
                double Ub  = ldv(&g_wacc[0]), Ut = ldv(&g_wacc[7]);
                double iUb = frcp(Ub), iUt = frcp(Ut);
                g_cc[0] = (float)(ldv(&g_wacc[2]) * iUb - ldv(&g_wacc[9])  * iUt);
                g_cc[1] = (float)(ldv(&g_wacc[3]) * iUb - ldv(&g_wacc[10]) * iUt);
                __threadfence();
                atomicExch(&g_flag, 1u);   // release
            }
        }
    }

    // ============ decode block -> (matrix, tile) ========================
    int mat, ti, tj;
    int t = -1;
    if (b < 2048) {
        if (b & 1) { int f = b >> 1; mat = 2; ti = f >> 5; tj = f & 31; }
        else t = b >> 1;
    } else t = 1024 + (b - 2048);
    if (t >= 0) {
        mat = (t < NTRI) ? 0 : 1;
        if (t >= NTRI) t -= NTRI;
        int r = 0;
        while (t >= NT - r) { t -= NT - r; r++; }
        ti = r; tj = r + t;
    }

    float delx = 0.f, dely = 0.f, del2 = 0.f;
    float x0, y0, u0, x1, y1, u1;
    int i0 = (ti << 8) + tid, i1 = i0 + 128;

    if (mat != 2) {
        // -------- same-cloud: everything computed locally, NO WAIT ------
        const float* pts = (mat == 1) ? target : base;
        #pragma unroll
        for (int tt = tid; tt < TILE; tt += 128) {
            float xj, yj, uj;
            mlp_xyu(pts, (tj << 8) + tt, sx, sy, w1, b1, w2, b2, xj, yj, uj);
            s_x[tt] = xj; s_y[tt] = yj; s_w[tt] = uj;
            s_q[tt] = m2 * fmaf(xj, xj, yj * yj);
        }
        mlp_xyu(pts, i0, sx, sy, w1, b1, w2, b2, x0, y0, u0);
        mlp_xyu(pts, i1, sx, sy, w1, b1, w2, b2, x1, y1, u1);
        __syncthreads();
    } else {
        // -------- cross: needs phase-1 results ---------------------------
        while (ld_acq(&g_flag) == 0u) __nanosleep(64);
        delx = g_cc[0]; dely = g_cc[1];
        del2 = delx * delx + dely * dely;
        #pragma unroll
        for (int tt = tid; tt < TILE; tt += 128) {
            int j = (tj << 8) + tt;
            float xj = g_px[1][j], yj = g_py[1][j];
            s_x[tt] = xj; s_y[tt] = yj;
            s_w[tt] = g_u[1][j];
            s_q[tt] = 2.f * (delx * xj + dely * yj);
        }
        x0 = g_px[0][i0]; y0 = g_py[0][i0]; u0 = g_u[0][i0];
        x1 = g_px[0][i1]; y1 = g_py[0][i1]; u1 = g_u[0][i1];
        __syncthreads();
    }

    float r00, r10, r20, r01, r11, r21, sds = 0.f;

    if (fast) {
        // 2 i-rows x 2 j-streams: 4 independent ex2->chain pipelines
        u64 A00 = 0, A10 = 0, A20 = 0, A01 = 0, A11 = 0, A21 = 0, SD = 0;
        if (mat != 2) {
            float q0 = m2 * fmaf(x0, x0, y0 * y0);
            float q1 = m2 * fmaf(x1, x1, y1 * y1);
            u64 X20 = pack2(-2.f * m2 * x0, -2.f * m2 * x0);
            u64 Y20 = pack2(-2.f * m2 * y0, -2.f * m2 * y0);
            u64 QI0 = pack2(q0, q0);
            u64 X21 = pack2(-2.f * m2 * x1, -2.f * m2 * x1);
            u64 Y21 = pack2(-2.f * m2 * y1, -2.f * m2 * y1);
            u64 QI1 = pack2(q1, q1);
            #pragma unroll 4
            for (int j = 0; j < 128; j += 2) {
                u64 xjA = *(const u64*)&s_x[j];
                u64 yjA = *(const u64*)&s_y[j];
                u64 qjA = *(const u64*)&s_q[j];
                u64 wjA = *(const u64*)&s_w[j];
                u64 xjB = *(const u64*)&s_x[j + 128];
                u64 yjB = *(const u64*)&s_y[j + 128];
                u64 qjB = *(const u64*)&s_q[j + 128];
                u64 wjB = *(const u64*)&s_w[j + 128];
                u64 a0A = add2(fma2(X20, xjA, fma2(Y20, yjA, qjA)), QI0);
                u64 a1A = add2(fma2(X21, xjA, fma2(Y21, yjA, qjA)), QI1);
                u64 a0B = add2(fma2(X20, xjB, fma2(Y20, yjB, qjB)), QI0);
                u64 a1B = add2(fma2(X21, xjB, fma2(Y21, yjB, qjB)), QI1);
                u64 e0A, e1A, e0B, e1B;
                EX2P(e0A, a0A); EX2P(e1A, a1A); EX2P(e0B, a0B); EX2P(e1B, a1B);
                CHAIN(e0A, wjA, A20, A10, A00);
                CHAIN(e1A, wjA, A21, A11, A01);
                CHAIN(e0B, wjB, A20, A10, A00);
                CHAIN(e1B, wjB, A21, A11, A01);
            }
        } else {
            float c0 = m2 * (del2 - 2.f * (delx * x0 + dely * y0));
            float c1 = m2 * (del2 - 2.f * (delx * x1 + dely * y1));
            u64 PX0 = pack2(x0, x0), PY0 = pack2(y0, y0), CI0 = pack2(c0, c0);
            u64 PX1 = pack2(x1, x1), PY1 = pack2(y1, y1), CI1 = pack2(c1, c1);
            u64 M2 = pack2(m2, m2);
            // sqrt stats half-sampled: stream A (j<128) only; finalize applies x2
            #pragma unroll 2
            for (int j = 0; j < 128; j += 2) {
                u64 xjA = *(const u64*)&s_x[j];
                u64 yjA = *(const u64*)&s_y[j];
                u64 kjA = *(const u64*)&s_q[j];
                u64 wjA = *(const u64*)&s_w[j];
                u64 xjB = *(const u64*)&s_x[j + 128];
                u64 yjB = *(const u64*)&s_y[j + 128];
                u64 kjB = *(const u64*)&s_q[j + 128];
                u64 wjB = *(const u64*)&s_w[j + 128];
                // stream A (with sqrt)
                u64 dx0 = sub2(PX0, xjA), dy0 = sub2(PY0, yjA);
                u64 d2r0 = fma2(dx0, dx0, mul2(dy0, dy0));
                float dl0, dh0; unpack2(d2r0, dl0, dh0);
                SD = add2(SD, pack2(sqrtap(dl0), sqrtap(dh0)));
                u64 a0A = fma2(add2(d2r0, kjA), M2, CI0);
                u64 dx1 = sub2(PX1, xjA), dy1 = sub2(PY1, yjA);
                u64 d2r1 = fma2(dx1, dx1, mul2(dy1, dy1));
                float dl1, dh1; unpack2(d2r1, dl1, dh1);
                SD = add2(SD, pack2(sqrtap(dl1), sqrtap(dh1)));
                u64 a1A = fma2(add2(d2r1, kjA), M2, CI1);
                // stream B (no sqrt)
                u64 dx0b = sub2(PX0, xjB), dy0b = sub2(PY0, yjB);
                u64 d2r0b = fma2(dx0b, dx0b, mul2(dy0b, dy0b));
                u64 a0B = fma2(add2(d2r0b, kjB), M2, CI0);
                u64 dx1b = sub2(PX1, xjB), dy1b = sub2(PY1, yjB);
                u64 d2r1b = fma2(dx1b, dx1b, mul2(dy1b, dy1b));
                u64 a1B = fma2(add2(d2r1b, kjB), M2, CI1);
                u64 e0A, e1A, e0B, e1B;
                EX2P(e0A, a0A); EX2P(e1A, a1A); EX2P(e0B, a0B); EX2P(e1B, a1B);
                CHAIN(e0A, wjA, A20, A10, A00);
                CHAIN(e1A, wjA, A21, A11, A01);
                CHAIN(e0B, wjB, A20, A10, A00);
                CHAIN(e1B, wjB, A21, A11, A01);
            }
        }
        float l, h;
        unpack2(A00, l, h); r00 = l + h;
        unpack2(A10, l, h); r10 = l + h;
        unpack2(A20, l, h); r20 = l + h;
        unpack2(A01, l, h); r01 = l + h;
        unpack2(A11, l, h); r11 = l + h;
        unpack2(A21, l, h); r21 = l + h;
        unpack2(SD,  l, h); sds = l + h;
    } else {
        // generic fallback
        r00 = r10 = r20 = r01 = r11 = r21 = 0.f;
        float sdfull = 0.f;
        for (int j = 0; j < TILE; j++) {
            float xj = s_x[j], yj = s_y[j], w = s_w[j];
            float dx0 = x0 - xj, dy0 = y0 - yj;
            float dx1 = x1 - xj, dy1 = y1 - yj;
            if (mat == 2) {
                float d2r0 = fmaf(dx0, dx0, dy0 * dy0);
                float d2r1 = fmaf(dx1, dx1, dy1 * dy1);
                sdfull += sqrtap(d2r0) + sqrtap(d2r1);
                dx0 -= delx; dy0 -= dely; dx1 -= delx; dy1 -= dely;
            }
            float d20 = fmaf(dx0, dx0, dy0 * dy0);
            float d21 = fmaf(dx1, dx1, dy1 * dy1);
            r00 = fmaf(w, ex2f(m0 * d20), r00);
            r10 = fmaf(w, ex2f(m1 * d20), r10);
            r20 = fmaf(w, ex2f(m2 * d20), r20);
            r01 = fmaf(w, ex2f(m0 * d21), r01);
            r11 = fmaf(w, ex2f(m1 * d21), r11);
            r21 = fmaf(w, ex2f(m2 * d21), r21);
        }
        sds = 0.5f * sdfull;   // finalize applies x2
    }

    float f = (mat != 2 && ti != tj) ? 2.f : 1.f;
    float w0 = f * u0, w1v = f * u1;
    float a0s = fmaf(w0, r00, w1v * r01);
    float a1s = fmaf(w0, r10, w1v * r11);
    float a2s = fmaf(w0, r20, w1v * r21);

    float r;
    r = block_reduce(a0s, sred); if (tid == 0) atomicAdd(&g_pacc[mat * 3 + 0], (double)r);
    r = block_reduce(a1s, sred); if (tid == 0) atomicAdd(&g_pacc[mat * 3 + 1], (double)r);
    r = block_reduce(a2s, sred); if (tid == 0) atomicAdd(&g_pacc[mat * 3 + 2], (double)r);
    if (mat == 2) {
        r = block_reduce(2.f * sds, sred);      // x2: half-sampled sqrt subset
        if (tid == 0) atomicAdd(&g_pacc[9], (double)r);
    }

    // ============ last block finalizes + re-zeroes state ================
    if (tid == 0) {
        __threadfence();
        unsigned old = atomicAdd(&g_ctr[1], 1u);
        slast = (old == NBLK - 1);
    }
    __syncthreads();
    if (slast && tid < 32) {
        __threadfence();
        int lane = tid;
        double Ub = ldv(&g_wacc[0]), U2b = ldv(&g_wacc[1]);
        double Ut = ldv(&g_wacc[7]), U2t = ldv(&g_wacc[8]);
        const double n = (double)N_PTS;
        const double invNM  = 1.0 / 67108864.0;   // 1/N^2
        const double invNM1 = 1.0 / 67108863.0;   // 1/(N^2-1)
        const double invn1  = 1.0 / 8191.0;

        double sum_d2 = n * (ldv(&g_wacc[6]) + ldv(&g_wacc[13]))
                      - 2.0 * (ldv(&g_wacc[4]) * ldv(&g_wacc[11])
                             + ldv(&g_wacc[5]) * ldv(&g_wacc[12]));
        double sd = ldv(&g_pacc[9]);
        double meand = sd * invNM;
        double vard  = (sum_d2 - sd * sd * invNM) * invNM1;

        double iUb = frcp(Ub), iUt = frcp(Ut);
        double iUb2 = iUb * iUb, iUt2 = iUt * iUt, iUbt = iUb * iUt;
        double wvar = (U2b * iUb2 - 1.0 / n) * invn1
                    + (U2t * iUt2 - 1.0 / n) * invn1;

        float stats[4] = { (float)meand, (float)vard, 0.f, (float)wvar };

        float L[3];
        #pragma unroll
        for (int k = 0; k < 3; k++)
            L[k] = (float)(ldv(&g_pacc[k]) * iUb2 + ldv(&g_pacc[3 + k]) * iUt2
                         - 2.0 * ldv(&g_pacc[6 + k]) * iUbt);

        float v = gb1[lane];
        #pragma unroll
        for (int d = 0; d < 4; d++) v = fmaf(stats[d], gw1[d * 32 + lane], v);
        float hrel = fmaxf(v, 0.f);

        float g[3], gs = 0.f;
        #pragma unroll
        for (int s = 0; s < 3; s++) {
            float p = hrel * gw2[lane * 3 + s];
            #pragma unroll
            for (int o = 16; o > 0; o >>= 1) p += __shfl_xor_sync(0xffffffffu, p, o);
            p += gb2[s];
            float sp = (p > 15.f) ? p : log1pf(__expf(p));
            g[s] = sp; gs += sp;
        }
        if (lane == 0) {
            float res = bias[0];
            float rgs = 1.f / gs;
            #pragma unroll
            for (int s = 0; s < 3; s++) res = fmaf(g[s] * rgs, L[s], res);
            out[0] = res;
        }

        // re-zero all device state for the next graph replay
        __syncwarp();
        if (lane < 14) *(volatile double*)&g_wacc[lane] = 0.0;
        if (lane < 10) *(volatile double*)&g_pacc[lane] = 0.0;
        if (lane < 2)  *(volatile unsigned*)&g_ctr[lane] = 0u;
        if (lane == 0) { __threadfence(); atomicExch(&g_flag, 0u); }
    }
}

// ---------------- launch ------------------------------------------------
extern "C" void kernel_launch(void* const* d_in, const int* in_sizes, int n_in,
                              void* d_out, int out_size)
{
    const float* base       = (const float*)d_in[0];
    const float* target     = (const float*)d_in[1];
    const float* log_sigmas = (const float*)d_in[2];
    const float* log_scale  = (const float*)d_in[3];
    const float* wn_w1      = (const float*)d_in[4];
    const float* wn_b1      = (const float*)d_in[5];
    const float* wn_w2      = (const float*)d_in[6];
    const float* wn_b2      = (const float*)d_in[7];
    const float* g_w1       = (const float*)d_in[8];
    const float* g_b1       = (const float*)d_in[9];
    const float* g_w2       = (const float*)d_in[10];
    const float* g_b2       = (const float*)d_in[11];
    const float* bias       = (const float*)d_in[12];

    k_fused<<<NBLK, 128>>>(base, target, log_scale, log_sigmas,
                           wn_w1, wn_b1, wn_w2, wn_b2,
                           g_w1, g_b1, g_w2, g_b2, bias, (float*)d_out);
}